// round 2
// baseline (speedup 1.0000x reference)
#include <cuda_runtime.h>
#include <stdint.h>

// Problem constants (fixed by the dataset)
#define NLAT_IN  181
#define NLON_IN  360
#define NLAT_OUT 91
#define NLON_OUT 180
#define KS       9        // kernel_size = (3-1)*4+1
#define B_       4
#define CIN      32
#define COUT     32
#define BC       128      // B_*CIN
#define CK       288      // CIN*KS
#define NPIX     (NLAT_IN * NLON_IN)   // 65160

#define WT       10       // longitudes per block (10 warps, 1 per w)
#define NWTILES  (NLON_OUT / WT)   // 18

#define MAXPIX   8192     // max unique pixels per output lat
#define MAXPAIR  32768    // max (k,psi) pairs per output lat

// ---------------- device scratch (no cudaMalloc allowed) ----------------
__device__ float g_xqt[NPIX * BC];                 // 33.4 MB: xq transposed [pix][bc]
__device__ float g_wt[CK * COUT];                  // W transposed [ck][o]
__device__ int   g_cnt[NLAT_OUT * NPIX];           // per-(h,pixel) counts -> pair offsets
__device__ int2  g_hdr[NLAT_OUT * MAXPIX];         // per-h pixel headers: ((row*360)<<9|lon, pairoff<<5|cnt)
__device__ int2  g_pairs[NLAT_OUT * MAXPAIR];      // (k, psi_bits)
__device__ int   g_npix[NLAT_OUT];
__device__ int   g_is64;                           // psi_idx dtype flag

// ---------------- dtype detection for psi_idx ----------------
__global__ void detect_kernel(const int* __restrict__ pidx, int nnz) {
    int bad = 0;
    for (int i = (nnz | 1); i < 2 * nnz; i += 64) bad |= pidx[i];
    g_is64 = (bad == 0) ? 1 : 0;
}

__device__ __forceinline__ void get_khf(const void* pidx, int nnz, int e,
                                        int is64, int& k, int& h, int& flat) {
    if (is64) {
        const long long* p = (const long long*)pidx;
        k = (int)p[e]; h = (int)p[(long long)nnz + e]; flat = (int)p[2LL * nnz + e];
    } else {
        const int* p = (const int*)pidx;
        k = p[e]; h = p[nnz + e]; flat = p[2 * nnz + e];
    }
}

// ---------------- zero the count array ----------------
__global__ void zero_kernel() {
    int i = blockIdx.x * blockDim.x + threadIdx.x;
    if (i < NLAT_OUT * NPIX) g_cnt[i] = 0;
}

// ---------------- count entries per (h, pixel) ----------------
__global__ void count_kernel(const void* __restrict__ pidx, int nnz) {
    int e = blockIdx.x * blockDim.x + threadIdx.x;
    if (e >= nnz) return;
    int k, h, flat;
    get_khf(pidx, nnz, e, g_is64, k, h, flat);
    atomicAdd(&g_cnt[h * NPIX + flat], 1);
}

// ---------------- per-h compaction: build headers + pair offsets ----------------
// one block per h, 1024 threads; chunked block scan over the 65160 pixel cells
__global__ void __launch_bounds__(1024) build_kernel() {
    int h = blockIdx.x;
    int t = threadIdx.x;
    int lane = t & 31, wid = t >> 5;
    __shared__ int s_wf[32], s_wc[32];
    __shared__ int s_pixbase, s_pairbase;
    if (t == 0) { s_pixbase = 0; s_pairbase = 0; }
    __syncthreads();
    int base = h * NPIX;
    for (int c0 = 0; c0 < NPIX; c0 += 1024) {
        int cell = c0 + t;
        int cnt = (cell < NPIX) ? g_cnt[base + cell] : 0;
        int flag = (cnt > 0) ? 1 : 0;
        int sf = flag, sc = cnt;
        #pragma unroll
        for (int o = 1; o < 32; o <<= 1) {
            int vf = __shfl_up_sync(~0u, sf, o);
            int vc = __shfl_up_sync(~0u, sc, o);
            if (lane >= o) { sf += vf; sc += vc; }
        }
        if (lane == 31) { s_wf[wid] = sf; s_wc[wid] = sc; }
        __syncthreads();
        if (wid == 0) {
            int wf = s_wf[lane], wc = s_wc[lane];
            #pragma unroll
            for (int o = 1; o < 32; o <<= 1) {
                int vf = __shfl_up_sync(~0u, wf, o);
                int vc = __shfl_up_sync(~0u, wc, o);
                if (lane >= o) { wf += vf; wc += vc; }
            }
            s_wf[lane] = wf; s_wc[lane] = wc;
        }
        __syncthreads();
        int exf = sf - flag + ((wid > 0) ? s_wf[wid - 1] : 0);
        int exc = sc - cnt + ((wid > 0) ? s_wc[wid - 1] : 0);
        int pixbase = s_pixbase, pairbase = s_pairbase;
        if (flag) {
            int slot = pixbase + exf;
            int pairoff = pairbase + exc;
            if (slot < MAXPIX && pairoff + cnt <= MAXPAIR) {
                int row = cell / NLON_IN;
                int lon = cell - row * NLON_IN;
                int2 hd;
                hd.x = ((row * NLON_IN) << 9) | lon;
                hd.y = (pairoff << 5) | cnt;
                g_hdr[h * MAXPIX + slot] = hd;
                g_cnt[base + cell] = pairoff;   // repurpose as scatter cursor
            }
        }
        __syncthreads();
        if (t == 0) {
            s_pixbase = s_pixbase + s_wf[31];
            s_pairbase = s_pairbase + s_wc[31];
        }
        __syncthreads();
    }
    if (t == 0) g_npix[h] = (s_pixbase < MAXPIX) ? s_pixbase : MAXPIX;
}

// ---------------- scatter (k, psi) pairs into groups ----------------
__global__ void scatter_kernel(const void* __restrict__ pidx,
                               const float* __restrict__ pvals, int nnz) {
    int e = blockIdx.x * blockDim.x + threadIdx.x;
    if (e >= nnz) return;
    int k, h, flat;
    get_khf(pidx, nnz, e, g_is64, k, h, flat);
    int slot = atomicAdd(&g_cnt[h * NPIX + flat], 1);
    if (slot >= 0 && slot < MAXPAIR) {
        int2 pr; pr.x = k; pr.y = __float_as_int(pvals[e]);
        g_pairs[h * MAXPAIR + slot] = pr;
    }
}

// ---------------- transpose + quad-weight scale: x -> xq_t[pix][bc] ----------------
__global__ void xq_kernel(const float* __restrict__ x, const float* __restrict__ qw) {
    __shared__ float tile[32][33];
    int row = blockIdx.z;
    int lon0 = blockIdx.x * 32;
    int bc0 = blockIdx.y * 32;
    int tx = threadIdx.x, ty = threadIdx.y;   // 32 x 8
    float q = qw[row];
    for (int i = ty; i < 32; i += 8) {
        int lon = lon0 + tx;
        float v = 0.f;
        if (lon < NLON_IN)
            v = x[((size_t)(bc0 + i) * NLAT_IN + row) * NLON_IN + lon];
        tile[i][tx] = v * q;
    }
    __syncthreads();
    for (int i = ty; i < 32; i += 8) {
        int lon = lon0 + i;
        if (lon < NLON_IN)
            g_xqt[((size_t)(row * NLON_IN + lon)) * BC + bc0 + tx] = tile[tx][i];
    }
}

// ---------------- transpose W: [o][ck] -> [ck][o] ----------------
__global__ void wt_kernel(const float* __restrict__ w) {
    int id = blockIdx.x * blockDim.x + threadIdx.x;
    if (id >= COUT * CK) return;
    int o = id / CK;
    int ck = id - o * CK;
    g_wt[ck * COUT + o] = w[id];
}

// ---------------- fused conv kernel ----------------
// grid: (NWTILES=18, NLAT_OUT=91), block: 320 threads = 10 warps (1 warp per w)
#define FMA4(A) { A.x = fmaf(pv, v0.x, A.x); A.y = fmaf(pv, v0.y, A.y); \
                  A.z = fmaf(pv, v0.z, A.z); A.w = fmaf(pv, v0.w, A.w); }
#define STK(kk, A) { s_acc[sb + 0 * KS + kk] = A.x; s_acc[sb + 1 * KS + kk] = A.y; \
                     s_acc[sb + 2 * KS + kk] = A.z; s_acc[sb + 3 * KS + kk] = A.w; }

__global__ void __launch_bounds__(WT * 32) conv_kernel(const float* __restrict__ bias,
                                                       float* __restrict__ out) {
    __shared__ float s_acc[WT * 4 * 289];   // [wslot*4 + b][ck], padded row 289

    int h = blockIdx.y;
    int wt = blockIdx.x;
    int lane = threadIdx.x & 31;
    int warp = threadIdx.x >> 5;            // wslot
    int w = wt * WT + warp;                 // global output longitude
    int tw = 2 * w;

    int boff = lane >> 3;                   // b (lane owns bc = lane*4 .. lane*4+3)
    int c0 = (lane & 7) * 4;
    int vbase = lane * 4;

    int np = g_npix[h];
    const int2* __restrict__ hdr = g_hdr + h * MAXPIX;
    const int2* __restrict__ prs = g_pairs + h * MAXPAIR;

    float4 a0 = {0,0,0,0}, a1 = a0, a2 = a0, a3 = a0, a4 = a0,
           a5 = a0, a6 = a0, a7 = a0, a8 = a0;

    // ---- stage 1: pixel-major traversal, 2-deep prefetch pipeline ----
    int2 hd = (np > 0) ? __ldg(&hdr[0]) : make_int2(0, 0);
    int col = (hd.x & 511) + tw; if (col >= NLON_IN) col -= NLON_IN;
    float4 v0 = (np > 0)
        ? __ldg((const float4*)&g_xqt[((size_t)((hd.x >> 9) + col)) * BC + vbase])
        : make_float4(0, 0, 0, 0);

    for (int p = 0; p < np; p++) {
        // prefetch next pixel's header + gather
        int2 hdn = hd; float4 vn = v0;
        if (p + 1 < np) {
            hdn = __ldg(&hdr[p + 1]);
            int cn = (hdn.x & 511) + tw; if (cn >= NLON_IN) cn -= NLON_IN;
            vn = __ldg((const float4*)&g_xqt[((size_t)((hdn.x >> 9) + cn)) * BC + vbase]);
        }
        int cnt = hd.y & 31;
        int po = hd.y >> 5;
        #pragma unroll 1
        for (int j = 0; j < cnt; j++) {
            int2 pr = __ldg(&prs[po + j]);
            float pv = __int_as_float(pr.y);
            switch (pr.x) {
                case 0: FMA4(a0); break;
                case 1: FMA4(a1); break;
                case 2: FMA4(a2); break;
                case 3: FMA4(a3); break;
                case 4: FMA4(a4); break;
                case 5: FMA4(a5); break;
                case 6: FMA4(a6); break;
                case 7: FMA4(a7); break;
                default: FMA4(a8); break;
            }
        }
        hd = hdn; v0 = vn;
    }

    int sb = (warp * 4 + boff) * 289 + c0 * KS;
    STK(0, a0); STK(1, a1); STK(2, a2); STK(3, a3); STK(4, a4);
    STK(5, a5); STK(6, a6); STK(7, a7); STK(8, a8);
    __syncthreads();

    // ---- stage 2: out[b,o,h,w] = sum_ck W[o][ck] * y[b][ck] ; lane = o ----
    float r0 = 0.f, r1 = 0.f, r2 = 0.f, r3 = 0.f;
    int slot0 = warp * 4;                   // 4 (w',b) slots per warp, 40 total
    const float* s0 = &s_acc[(slot0 + 0) * 289];
    const float* s1 = &s_acc[(slot0 + 1) * 289];
    const float* s2 = &s_acc[(slot0 + 2) * 289];
    const float* s3 = &s_acc[(slot0 + 3) * 289];
    #pragma unroll 4
    for (int ck = 0; ck < CK; ck++) {
        float wv = g_wt[ck * COUT + lane];
        r0 = fmaf(wv, s0[ck], r0);
        r1 = fmaf(wv, s1[ck], r1);
        r2 = fmaf(wv, s2[ck], r2);
        r3 = fmaf(wv, s3[ck], r3);
    }
    float bo = bias[lane];
    float rr[4] = {r0, r1, r2, r3};
    #pragma unroll
    for (int p = 0; p < 4; p++) {
        int slot = slot0 + p;
        int wp = slot >> 2;                 // local wslot
        int bp = slot & 3;                  // b
        out[(((size_t)(bp * COUT + lane)) * NLAT_OUT + h) * NLON_OUT + (wt * WT + wp)]
            = rr[p] + bo;
    }
}

// ---------------- launch ----------------
extern "C" void kernel_launch(void* const* d_in, const int* in_sizes, int n_in,
                              void* d_out, int out_size) {
    const float* x      = (const float*)d_in[0];
    const float* qw     = (const float*)d_in[1];
    const float* pvals  = (const float*)d_in[2];
    const float* weight = (const float*)d_in[3];
    const float* bias   = (const float*)d_in[4];
    const void*  pidx   = d_in[5];
    float* out = (float*)d_out;

    int nnz = in_sizes[2];   // psi_vals element count
    int tb = 256;

    detect_kernel<<<1, 1>>>((const int*)pidx, nnz);
    zero_kernel<<<(NLAT_OUT * NPIX + 1023) / 1024, 1024>>>();
    count_kernel<<<(nnz + tb - 1) / tb, tb>>>(pidx, nnz);
    build_kernel<<<NLAT_OUT, 1024>>>();
    scatter_kernel<<<(nnz + tb - 1) / tb, tb>>>(pidx, pvals, nnz);

    dim3 xg((NLON_IN + 31) / 32, BC / 32, NLAT_IN);   // (12, 4, 181)
    xq_kernel<<<xg, dim3(32, 8)>>>(x, qw);

    wt_kernel<<<(COUT * CK + 255) / 256, 256>>>(weight);

    conv_kernel<<<dim3(NWTILES, NLAT_OUT), WT * 32>>>(bias, out);
}